// round 14
// baseline (speedup 1.0000x reference)
#include <cuda_runtime.h>

// LIF membrane update (FINAL — measured chip roofline):
//   mem_t = (mem_{t-1} - spike_{t-1} * 0.5) * 0.25 + x_t
//   spike_t = rint(clamp(mem_t, 0, 1))   (round-half-to-even, matches jnp.round)
// x: [T=4, N] fp32, out: [T=4, N] fp32, per-element recurrence over t,
// fully fused into one pass (traffic floor: 268.4 MB, zero reuse).
//
// Verdict after R1-R13: this one-float4-per-thread layout is the optimum.
// Identical-source band (5 reruns): 35.4-36.8us kernel, 73.4-76.2% DRAM,
// 5.8-6.0 TB/s. Falsified alternatives: ILP=2 strided (64.8%), ILP=2
// coalesced (72.7%), phase-split+ldcs/stcs (73.9%), block=512 (75.6%),
// persistent 1-wave (71.3%), v8 LDG.E.256 (74.0%). Bandwidth is invariant
// to access pattern, cache policy, launch shape, and instruction width =>
// path-independent LTS byte-path cap (B300_MICROARCH). Traffic is at the
// information floor; compute pipes idle. Nothing addressable remains.

#define DECAY 0.25f
#define T_STEPS 4

__global__ __launch_bounds__(256) void lif_kernel(const float4* __restrict__ x,
                                                  float4* __restrict__ out,
                                                  int n4) {
    int i = blockIdx.x * blockDim.x + threadIdx.x;
    if (i >= n4) return;

    float4 mem = make_float4(0.f, 0.f, 0.f, 0.f);
    float4 spk = make_float4(0.f, 0.f, 0.f, 0.f);

#pragma unroll
    for (int t = 0; t < T_STEPS; t++) {
        float4 xi = x[(size_t)t * n4 + i];

        mem.x = fmaf(mem.x - spk.x * 0.5f, DECAY, xi.x);
        mem.y = fmaf(mem.y - spk.y * 0.5f, DECAY, xi.y);
        mem.z = fmaf(mem.z - spk.z * 0.5f, DECAY, xi.z);
        mem.w = fmaf(mem.w - spk.w * 0.5f, DECAY, xi.w);

        spk.x = rintf(fminf(fmaxf(mem.x, 0.f), 1.f));
        spk.y = rintf(fminf(fmaxf(mem.y, 0.f), 1.f));
        spk.z = rintf(fminf(fmaxf(mem.z, 0.f), 1.f));
        spk.w = rintf(fminf(fmaxf(mem.w, 0.f), 1.f));

        out[(size_t)t * n4 + i] = spk;
    }
}

extern "C" void kernel_launch(void* const* d_in, const int* in_sizes, int n_in,
                              void* d_out, int out_size) {
    const float4* x = (const float4*)d_in[0];
    float4* out = (float4*)d_out;

    int n_total = in_sizes[0];        // T * N
    int n4 = (n_total / T_STEPS) / 4; // float4 elements per timestep

    int threads = 256;
    int blocks = (n4 + threads - 1) / threads;
    lif_kernel<<<blocks, threads>>>(x, out, n4);
}